// round 9
// baseline (speedup 1.0000x reference)
#include <cuda_runtime.h>

#define N_TOK 1024
#define HD    256
#define ED    128
#define TN    12
#define ON    3
#define NHOPS 4
#define NB    36
#define W1STR (384*256)
#define W2STR (256*256)
#define MTILE 16
#define MAXT  100        // max tiles/hop: 1024/16 + 36 partials
#define XS_STR 260       // floats; 16B-aligned rows, conflict-benign
#define KB    32         // K-rows per smem chunk
#define NCH   (HD/KB)    // 8 chunks

// ---- scratch (no device allocation allowed) ----
__device__ float g_state[N_TOK * HD];
__device__ float g_h[N_TOK * HD];
__device__ float g_b1eff[NB * HD];
__device__ int   g_perm[NHOPS][N_TOK];
__device__ int   g_tile_info[NHOPS][MAXT];   // bkt | poff<<6 | mcnt<<17
__device__ int   g_ntiles[NHOPS];

// ============================================================
// 0) fused prep: blocks 0..255 copy x->g_state (reshape identity),
//    blocks 256..291 fold op-emb half of W1 + b1 -> g_b1eff,
//    block 292 buckets all 4 hops (atomics; output order-invariant).
// ============================================================
__global__ void __launch_bounds__(256)
prep_kernel(const float* __restrict__ x,
            const float* __restrict__ W1, const float* __restrict__ b1,
            const float* __restrict__ emb,
            const int* __restrict__ st, const int* __restrict__ so) {
    int blk = blockIdx.x, tid = threadIdx.x;
    if (blk < 256) {
        int i = blk * 256 + tid;
        ((float4*)g_state)[i] = ((const float4*)x)[i];
    } else if (blk < 256 + NB) {
        int bkt = blk - 256, o = tid;
        const float* wE = W1 + (size_t)bkt * W1STR + 256 * HD + o;
        const float* ev = emb + bkt * ED;
        float acc = b1[bkt * HD + o];
#pragma unroll 8
        for (int e = 0; e < ED; e++) acc += ev[e] * wE[e * HD];
        g_b1eff[bkt * HD + o] = acc;
    } else {
        __shared__ int cnt[NB];
        __shared__ int base[NB];
        bool act[4] = {true, true, true, true};
        for (int hop = 0; hop < NHOPS; hop++) {
            if (tid < NB) cnt[tid] = 0;
            __syncthreads();
            int bb[4], rr[4];
#pragma unroll
            for (int j = 0; j < 4; j++) {
                int n = tid + 256 * j;
                act[j] = act[j] && (st[hop * N_TOK + n] != TN);
                if (act[j]) {
                    bb[j] = st[hop * N_TOK + n] * ON + so[hop * N_TOK + n];
                    rr[j] = atomicAdd(&cnt[bb[j]], 1);
                }
            }
            __syncthreads();
            if (tid == 0) {
                int s = 0, nt = 0;
                for (int i = 0; i < NB; i++) {
                    base[i] = s;
                    int c = cnt[i];
                    for (int off = 0; off < c; off += MTILE) {
                        int mc = c - off; if (mc > MTILE) mc = MTILE;
                        g_tile_info[hop][nt++] = i | ((s + off) << 6) | (mc << 17);
                    }
                    s += c;
                }
                g_ntiles[hop] = nt;
            }
            __syncthreads();
#pragma unroll
            for (int j = 0; j < 4; j++)
                if (act[j]) g_perm[hop][base[bb[j]] + rr[j]] = tid + 256 * j;
            __syncthreads();
        }
    }
}

// ============================================================
// 1) grouped FFN layer, K=256.  CTA = 16 tokens x 64 outputs,
//    256 threads, thread = 1 tok x 4 out.  DENSE 1D grid mapping:
//    bid -> (tile = bid>>2, outBase = (bid&3)*64); live CTAs are
//    contiguous from bid 0 -> ~288 live CTAs = 2 CTAs/SM in ONE
//    wave (4 warps/SMSP: cross-CTA latency/barrier hiding).
//    W staged in smem, KB=32 double-buffered chunks.
// ============================================================
template <bool L1>
__global__ void __launch_bounds__(256)
ffn_kernel(int hop, const float* __restrict__ W, const float* __restrict__ b2) {
    __shared__ float xs[MTILE * XS_STR];
    __shared__ float ws[2][KB * 64];
    __shared__ float cs[64];
    __shared__ int   tok_s[MTILE];

    int bid = blockIdx.x;
    if (bid >= 4 * g_ntiles[hop]) return;   // dead tail exits instantly
    int tix = bid >> 2;
    int outBase = (bid & 3) << 6;

    int info = g_tile_info[hop][tix];
    int bkt  = info & 63;
    int poff = (info >> 6) & 2047;
    int mcnt = info >> 17;
    int tid = threadIdx.x;

    const float* in   = L1 ? g_state : g_h;
    float*       outp = L1 ? g_h     : g_state;
    const float* bias = L1 ? g_b1eff : b2;
    const float* Wb   = W + (size_t)bkt * (L1 ? W1STR : W2STR);

    if (tid < MTILE) tok_s[tid] = (tid < mcnt) ? g_perm[hop][poff + tid] : -1;
    if (tid < 64)    cs[tid] = bias[bkt * HD + outBase + tid];
    __syncthreads();

    // gather x tile (float4; zero-pad dead rows): 16 rows x 64 float4
    {
        int r = tid >> 4, c4g = (tid & 15) << 2;
#pragma unroll
        for (int rep = 0; rep < 4; rep++) {
            float4 v = (tok_s[r] >= 0)
                ? *(const float4*)(in + tok_s[r] * HD + (c4g + rep) * 4)
                : make_float4(0.f, 0.f, 0.f, 0.f);
            *(float4*)(xs + r * XS_STR + (c4g + rep) * 4) = v;
        }
    }

    // stage W chunk 0 (2 coalesced float4 LDG / thread)
    int r0 = tid >> 4, c4 = tid & 15;
    const float* wsrc = Wb + outBase + c4 * 4;
    {
        float4 p0 = *(const float4*)(wsrc + r0 * HD);
        float4 p1 = *(const float4*)(wsrc + (r0 + 16) * HD);
        *(float4*)(&ws[0][r0 * 64 + c4 * 4])        = p0;
        *(float4*)(&ws[0][(r0 + 16) * 64 + c4 * 4]) = p1;
    }
    __syncthreads();

    int og = tid & 15, tok = tid >> 4;
    const float* xr = xs + tok * XS_STR;
    float a0 = 0.f, a1 = 0.f, a2 = 0.f, a3 = 0.f;

#pragma unroll
    for (int ch = 0; ch < NCH; ch++) {
        float4 q0, q1;
        if (ch < NCH - 1) {
            q0 = *(const float4*)(wsrc + (KB * (ch + 1) + r0) * HD);
            q1 = *(const float4*)(wsrc + (KB * (ch + 1) + r0 + 16) * HD);
        }
        const float* wb = &ws[ch & 1][og * 4];
#pragma unroll
        for (int k4 = 0; k4 < KB / 4; k4++) {
            float4 xv = *(const float4*)(xr + ch * KB + k4 * 4);
#pragma unroll
            for (int j = 0; j < 4; j++) {
                float4 w = *(const float4*)(wb + (k4 * 4 + j) * 64);
                float xj = (j == 0) ? xv.x : (j == 1) ? xv.y : (j == 2) ? xv.z : xv.w;
                a0 += xj * w.x; a1 += xj * w.y; a2 += xj * w.z; a3 += xj * w.w;
            }
        }
        if (ch < NCH - 1) {
            *(float4*)(&ws[(ch + 1) & 1][r0 * 64 + c4 * 4])        = q0;
            *(float4*)(&ws[(ch + 1) & 1][(r0 + 16) * 64 + c4 * 4]) = q1;
            __syncthreads();
        }
    }

    if (tok < mcnt) {
        int ob = outBase + og * 4;
        float4 r;
        r.x = fmaxf(a0 + cs[og * 4 + 0], 0.f);
        r.y = fmaxf(a1 + cs[og * 4 + 1], 0.f);
        r.z = fmaxf(a2 + cs[og * 4 + 2], 0.f);
        r.w = fmaxf(a3 + cs[og * 4 + 3], 0.f);
        *(float4*)(outp + tok_s[tok] * HD + ob) = r;
    }
}

// ============================================================
// 2) pool(8) + LayerNorm + 256x10 head.  Deterministic shuffle trees.
// ============================================================
__global__ void __launch_bounds__(256)
head_kernel(const float* __restrict__ ln_g, const float* __restrict__ ln_b,
            const float* __restrict__ Wt,   const float* __restrict__ bt,
            float* __restrict__ out) {
    int b = blockIdx.x, col = threadIdx.x;
    float s = 0.f;
#pragma unroll
    for (int p = 0; p < 8; p++) s += g_state[(b * 8 + p) * HD + col];
    float pooled = s * 0.125f;

    float v = pooled, v2 = pooled * pooled;
#pragma unroll
    for (int off = 16; off; off >>= 1) {
        v  += __shfl_down_sync(0xffffffffu, v,  off);
        v2 += __shfl_down_sync(0xffffffffu, v2, off);
    }
    __shared__ float wsum[8], wsum2[8];
    __shared__ float mu_s, rstd_s;
    int w = col >> 5, l = col & 31;
    if (l == 0) { wsum[w] = v; wsum2[w] = v2; }
    __syncthreads();
    if (col == 0) {
        float S = 0.f, S2 = 0.f;
#pragma unroll
        for (int i = 0; i < 8; i++) { S += wsum[i]; S2 += wsum2[i]; }
        float mu  = S * (1.f / 256.f);
        float var = S2 * (1.f / 256.f) - mu * mu;
        mu_s = mu; rstd_s = rsqrtf(var + 1e-5f);
    }
    __syncthreads();
    float normed = (pooled - mu_s) * rstd_s * ln_g[col] + ln_b[col];

    float p[10];
#pragma unroll
    for (int c = 0; c < 10; c++) p[c] = normed * Wt[col * 10 + c];
#pragma unroll
    for (int off = 16; off; off >>= 1)
#pragma unroll
        for (int c = 0; c < 10; c++) p[c] += __shfl_down_sync(0xffffffffu, p[c], off);

    __shared__ float pr[8][10];
    if (l == 0)
#pragma unroll
        for (int c = 0; c < 10; c++) pr[w][c] = p[c];
    __syncthreads();
    if (col < 10) {
        float acc = bt[col];
#pragma unroll
        for (int i = 0; i < 8; i++) acc += pr[i][col];
        out[b * 10 + col] = acc;
    }
}

// ============================================================
extern "C" void kernel_launch(void* const* d_in, const int* in_sizes, int n_in,
                              void* d_out, int out_size) {
    const float* x    = (const float*)d_in[0];
    const float* W1   = (const float*)d_in[1];
    const float* b1   = (const float*)d_in[2];
    const float* W2   = (const float*)d_in[3];
    const float* b2   = (const float*)d_in[4];
    const float* emb  = (const float*)d_in[5];
    const float* ln_g = (const float*)d_in[6];
    const float* ln_b = (const float*)d_in[7];
    const float* Wt   = (const float*)d_in[8];
    const float* bt   = (const float*)d_in[9];
    const int*   st   = (const int*)d_in[10];
    const int*   so   = (const int*)d_in[11];
    float* out = (float*)d_out;
    (void)in_sizes; (void)n_in; (void)out_size;

    prep_kernel<<<256 + NB + 1, 256>>>(x, W1, b1, emb, st, so);
    for (int hop = 0; hop < NHOPS; hop++) {
        ffn_kernel<true ><<<4 * MAXT, 256>>>(hop, W1, b2);
        ffn_kernel<false><<<4 * MAXT, 256>>>(hop, W2, b2);
    }
    head_kernel<<<128, 256>>>(ln_g, ln_b, Wt, bt, out);
}

// round 14
// speedup vs baseline: 1.1172x; 1.1172x over previous
#include <cuda_runtime.h>

#define N_TOK 1024
#define HD    256
#define ED    128
#define TN    12
#define ON    3
#define NHOPS 4
#define NB    36
#define W1STR (384*256)
#define W2STR (256*256)
#define MTILE 32
#define MAXT  68
#define XS_STR 260
#define KB    16          // K-rows per smem chunk (static smem < 48KB)
#define NCH   (HD/KB)     // 16 chunks
#define GRID  148         // <= SM count: all CTAs co-resident (1/SM)

// ---- scratch (no device allocation allowed) ----
__device__ float g_state[N_TOK * HD];
__device__ float g_h[N_TOK * HD];
__device__ float g_b1eff[NB * HD];
__device__ int   g_perm[NHOPS][N_TOK];
__device__ int   g_tinfo[NHOPS][MAXT];   // bkt | poff<<6 | mcnt<<17
__device__ int   g_ntiles[NHOPS];
__device__ unsigned g_arrive;            // monotonic across graph replays

// Reset-free, replay-safe grid barrier. Arrival #my belongs to barrier
// instance (my-1)/GRID; all arrivals of instance i complete before any
// arrival of instance i+1 can occur (CTAs block at each barrier), so the
// counter partitions into clean GRID-blocks and never needs resetting.
__device__ __forceinline__ void grid_bar() {
    __syncthreads();
    if (threadIdx.x == 0) {
        __threadfence();                       // release
        unsigned my = atomicAdd(&g_arrive, 1u) + 1u;
        unsigned target = (((my - 1u) / GRID) + 1u) * GRID;
        while (*((volatile unsigned*)&g_arrive) < target) __nanosleep(64);
        __threadfence();                       // acquire
    }
    __syncthreads();
}

// ============================================================
// Grouped FFN layer phase (R8-proven config).  Dense tile map:
// bid -> (tile = bid>>2, outBase = (bid&3)*64); grid-stride over
// live tiles (typically <=148 -> one pass).  In/out through L2
// (__ldcg) since L1 is stale across phases within one launch.
// ============================================================
__device__ void gemm_phase(int hop, const float* __restrict__ in,
                           float* __restrict__ outp,
                           const float* __restrict__ W, int wstride,
                           const float* __restrict__ bias,
                           float* xs, float* ws, float* cs, int* tok_s) {
    int tid = threadIdx.x;
    int nt4 = 4 * __ldcg(&g_ntiles[hop]);
    for (int bid = blockIdx.x; bid < nt4; bid += GRID) {
        __syncthreads();                 // protect smem reuse across tiles
        int tix = bid >> 2;
        int outBase = (bid & 3) << 6;
        int info = __ldcg(&g_tinfo[hop][tix]);
        int bkt  = info & 63;
        int poff = (info >> 6) & 2047;
        int mcnt = info >> 17;
        const float* Wb = W + (size_t)bkt * wstride;

        if (tid < MTILE) tok_s[tid] = (tid < mcnt) ? __ldcg(&g_perm[hop][poff + tid]) : -1;
        if (tid < 64)    cs[tid] = __ldcg(&bias[bkt * HD + outBase + tid]);
        __syncthreads();

        // gather x tile via L2 (float4; zero-pad dead rows)
        for (int i = tid; i < MTILE * 64; i += 256) {
            int r = i >> 6, c4 = i & 63;
            float4 v = (tok_s[r] >= 0)
                ? __ldcg((const float4*)(in + tok_s[r] * HD + c4 * 4))
                : make_float4(0.f, 0.f, 0.f, 0.f);
            *(float4*)(xs + r * XS_STR + c4 * 4) = v;
        }

        // stage W chunk 0 (1 coalesced float4 LDG / thread; W is read-only)
        int r0 = tid >> 4, c4 = tid & 15;
        const float* wsrc = Wb + outBase + c4 * 4;
        *(float4*)(ws + r0 * 64 + c4 * 4) = *(const float4*)(wsrc + r0 * HD);
        __syncthreads();

        int og = tid & 15, tg = tid >> 4;
        const float* xr0 = xs + tg * XS_STR;
        const float* xr1 = xs + (tg + 16) * XS_STR;
        float a00 = 0.f, a01 = 0.f, a02 = 0.f, a03 = 0.f;
        float a10 = 0.f, a11 = 0.f, a12 = 0.f, a13 = 0.f;

#pragma unroll
        for (int ch = 0; ch < NCH; ch++) {
            float4 q;
            if (ch < NCH - 1)
                q = *(const float4*)(wsrc + (KB * (ch + 1) + r0) * HD);
            const float* wb = ws + (ch & 1) * (KB * 64) + og * 4;
#pragma unroll
            for (int k4 = 0; k4 < KB / 4; k4++) {
                float4 xv0 = *(const float4*)(xr0 + ch * KB + k4 * 4);
                float4 xv1 = *(const float4*)(xr1 + ch * KB + k4 * 4);
#pragma unroll
                for (int j = 0; j < 4; j++) {
                    float4 w = *(const float4*)(wb + (k4 * 4 + j) * 64);
                    float x0 = (j == 0) ? xv0.x : (j == 1) ? xv0.y : (j == 2) ? xv0.z : xv0.w;
                    float x1 = (j == 0) ? xv1.x : (j == 1) ? xv1.y : (j == 2) ? xv1.z : xv1.w;
                    a00 += x0 * w.x; a01 += x0 * w.y; a02 += x0 * w.z; a03 += x0 * w.w;
                    a10 += x1 * w.x; a11 += x1 * w.y; a12 += x1 * w.z; a13 += x1 * w.w;
                }
            }
            if (ch < NCH - 1) {
                *(float4*)(ws + ((ch + 1) & 1) * (KB * 64) + r0 * 64 + c4 * 4) = q;
                __syncthreads();
            }
        }

        float c0 = cs[og * 4 + 0], c1 = cs[og * 4 + 1];
        float c2 = cs[og * 4 + 2], c3 = cs[og * 4 + 3];
        int ob = outBase + og * 4;
        if (tg < mcnt) {
            float4 r;
            r.x = fmaxf(a00 + c0, 0.f); r.y = fmaxf(a01 + c1, 0.f);
            r.z = fmaxf(a02 + c2, 0.f); r.w = fmaxf(a03 + c3, 0.f);
            *(float4*)(outp + tok_s[tg] * HD + ob) = r;
        }
        if (tg + 16 < mcnt) {
            float4 r;
            r.x = fmaxf(a10 + c0, 0.f); r.y = fmaxf(a11 + c1, 0.f);
            r.z = fmaxf(a12 + c2, 0.f); r.w = fmaxf(a13 + c3, 0.f);
            *(float4*)(outp + tok_s[tg + 16] * HD + ob) = r;
        }
    }
}

// ============================================================
// Single persistent kernel: prep | 8 GEMM phases | head, with
// device-side global barriers instead of kernel boundaries.
// ============================================================
__global__ void __launch_bounds__(256, 1)
temper_kernel(const float* __restrict__ x,
              const float* __restrict__ W1, const float* __restrict__ b1,
              const float* __restrict__ W2, const float* __restrict__ b2,
              const float* __restrict__ emb,
              const float* __restrict__ ln_g, const float* __restrict__ ln_b,
              const float* __restrict__ Wt,  const float* __restrict__ bt,
              const int* __restrict__ st, const int* __restrict__ so,
              float* __restrict__ out) {
    __shared__ float xs[MTILE * XS_STR];   // 33280 B
    __shared__ float ws[2 * KB * 64];      //  8192 B
    __shared__ float cs[64];
    __shared__ int   tok_s[MTILE];
    __shared__ int   cnt[NB], basev[NB];
    __shared__ float wsum[8], wsum2[8], mu_s, rstd_s;
    __shared__ float pr[8][10];

    int bid = blockIdx.x, tid = threadIdx.x;

    // ---------- phase 0: prep ----------
    // all CTAs: copy x -> g_state (reshape is identity), float4
    for (int i = bid * 256 + tid; i < N_TOK * HD / 4; i += GRID * 256)
        ((float4*)g_state)[i] = *((const float4*)x + i);

    // CTAs 0..35: fold op-emb half of W1 + b1 -> g_b1eff (hop-invariant)
    if (bid < NB) {
        int o = tid;
        const float* wE = W1 + (size_t)bid * W1STR + 256 * HD + o;
        const float* ev = emb + bid * ED;
        float acc = b1[bid * HD + o];
#pragma unroll 8
        for (int e = 0; e < ED; e++) acc += ev[e] * wE[e * HD];
        g_b1eff[bid * HD + o] = acc;
    }

    // CTA 147: bucket all 4 hops (atomics; results order-invariant)
    if (bid == GRID - 1) {
        bool act[4] = {true, true, true, true};
        for (int hop = 0; hop < NHOPS; hop++) {
            if (tid < NB) cnt[tid] = 0;
            __syncthreads();
            int bb[4], rr[4];
#pragma unroll
            for (int j = 0; j < 4; j++) {
                int n = tid + 256 * j;
                act[j] = act[j] && (st[hop * N_TOK + n] != TN);
                if (act[j]) {
                    bb[j] = st[hop * N_TOK + n] * ON + so[hop * N_TOK + n];
                    rr[j] = atomicAdd(&cnt[bb[j]], 1);
                }
            }
            __syncthreads();
            if (tid == 0) {
                int s = 0, nt = 0;
                for (int i = 0; i < NB; i++) {
                    basev[i] = s;
                    int c = cnt[i];
                    for (int off = 0; off < c; off += MTILE) {
                        int mc = c - off; if (mc > MTILE) mc = MTILE;
                        g_tinfo[hop][nt++] = i | ((s + off) << 6) | (mc << 17);
                    }
                    s += c;
                }
                g_ntiles[hop] = nt;
            }
            __syncthreads();
#pragma unroll
            for (int j = 0; j < 4; j++)
                if (act[j]) g_perm[hop][basev[bb[j]] + rr[j]] = tid + 256 * j;
            __syncthreads();
        }
    }
    grid_bar();

    // ---------- phases 1..8: 4 hops x 2 layers ----------
    for (int hop = 0; hop < NHOPS; hop++) {
        gemm_phase(hop, g_state, g_h, W1, W1STR, g_b1eff, xs, ws, cs, tok_s);
        grid_bar();
        gemm_phase(hop, g_h, g_state, W2, W2STR, b2, xs, ws, cs, tok_s);
        grid_bar();
    }

    // ---------- phase 9: pool(8) + LayerNorm + 256x10 head ----------
    if (bid < 128) {
        int b = bid, col = tid;
        float s = 0.f;
#pragma unroll
        for (int p = 0; p < 8; p++) s += __ldcg(&g_state[(b * 8 + p) * HD + col]);
        float pooled = s * 0.125f;

        float v = pooled, v2 = pooled * pooled;
#pragma unroll
        for (int off = 16; off; off >>= 1) {
            v  += __shfl_down_sync(0xffffffffu, v,  off);
            v2 += __shfl_down_sync(0xffffffffu, v2, off);
        }
        int w = col >> 5, l = col & 31;
        if (l == 0) { wsum[w] = v; wsum2[w] = v2; }
        __syncthreads();
        if (col == 0) {
            float S = 0.f, S2 = 0.f;
#pragma unroll
            for (int i = 0; i < 8; i++) { S += wsum[i]; S2 += wsum2[i]; }
            float mu  = S * (1.f / 256.f);
            float var = S2 * (1.f / 256.f) - mu * mu;
            mu_s = mu; rstd_s = rsqrtf(var + 1e-5f);
        }
        __syncthreads();
        float normed = (pooled - mu_s) * rstd_s * ln_g[col] + ln_b[col];

        float p[10];
#pragma unroll
        for (int c = 0; c < 10; c++) p[c] = normed * Wt[col * 10 + c];
#pragma unroll
        for (int off = 16; off; off >>= 1)
#pragma unroll
            for (int c = 0; c < 10; c++) p[c] += __shfl_down_sync(0xffffffffu, p[c], off);

        if (l == 0)
#pragma unroll
            for (int c = 0; c < 10; c++) pr[w][c] = p[c];
        __syncthreads();
        if (col < 10) {
            float acc = bt[col];
#pragma unroll
            for (int i = 0; i < 8; i++) acc += pr[i][col];
            out[b * 10 + col] = acc;
        }
    }
}

// ============================================================
extern "C" void kernel_launch(void* const* d_in, const int* in_sizes, int n_in,
                              void* d_out, int out_size) {
    const float* x    = (const float*)d_in[0];
    const float* W1   = (const float*)d_in[1];
    const float* b1   = (const float*)d_in[2];
    const float* W2   = (const float*)d_in[3];
    const float* b2   = (const float*)d_in[4];
    const float* emb  = (const float*)d_in[5];
    const float* ln_g = (const float*)d_in[6];
    const float* ln_b = (const float*)d_in[7];
    const float* Wt   = (const float*)d_in[8];
    const float* bt   = (const float*)d_in[9];
    const int*   st   = (const int*)d_in[10];
    const int*   so   = (const int*)d_in[11];
    float* out = (float*)d_out;
    (void)in_sizes; (void)n_in; (void)out_size;

    temper_kernel<<<GRID, 256>>>(x, W1, b1, W2, b2, emb,
                                 ln_g, ln_b, Wt, bt, st, so, out);
}

// round 15
// speedup vs baseline: 1.4637x; 1.3101x over previous
#include <cuda_runtime.h>

#define N_TOK 1024
#define HD    256
#define ED    128
#define TN    12
#define ON    3
#define NHOPS 4
#define NB    36
#define W1STR (384*256)
#define W2STR (256*256)
#define MTILE 8           // tokens per fused tile (both layers in-CTA)
#define MAXT  164         // max tiles/hop: 1024/8 + 36 partials
#define XS_STR 260
#define KBF   8           // K-rows per W smem chunk
#define NCHF  (HD/KBF)    // 32 chunks

// ---- scratch (no device allocation allowed) ----
__device__ float g_state[N_TOK * HD];
__device__ float g_b1eff[NB * HD];
__device__ int   g_perm[NHOPS][N_TOK];
__device__ int   g_tinfo[NHOPS][MAXT];   // bkt | poff<<6 | mcnt<<17
__device__ int   g_ntiles[NHOPS];

// ============================================================
// 0) fused prep: blocks 0..255 copy x->g_state (reshape identity),
//    blocks 256..291 fold op-emb half of W1 + b1 -> g_b1eff,
//    block 292 buckets all 4 hops (atomics; output order-invariant).
// ============================================================
__global__ void __launch_bounds__(256)
prep_kernel(const float* __restrict__ x,
            const float* __restrict__ W1, const float* __restrict__ b1,
            const float* __restrict__ emb,
            const int* __restrict__ st, const int* __restrict__ so) {
    int blk = blockIdx.x, tid = threadIdx.x;
    if (blk < 256) {
        int i = blk * 256 + tid;
        ((float4*)g_state)[i] = ((const float4*)x)[i];
    } else if (blk < 256 + NB) {
        int bkt = blk - 256, o = tid;
        const float* wE = W1 + (size_t)bkt * W1STR + 256 * HD + o;
        const float* ev = emb + bkt * ED;
        float acc = b1[bkt * HD + o];
#pragma unroll 8
        for (int e = 0; e < ED; e++) acc += ev[e] * wE[e * HD];
        g_b1eff[bkt * HD + o] = acc;
    } else {
        __shared__ int cnt[NB];
        __shared__ int base[NB];
        bool act[4] = {true, true, true, true};
        for (int hop = 0; hop < NHOPS; hop++) {
            if (tid < NB) cnt[tid] = 0;
            __syncthreads();
            int bb[4], rr[4];
#pragma unroll
            for (int j = 0; j < 4; j++) {
                int n = tid + 256 * j;
                act[j] = act[j] && (st[hop * N_TOK + n] != TN);
                if (act[j]) {
                    bb[j] = st[hop * N_TOK + n] * ON + so[hop * N_TOK + n];
                    rr[j] = atomicAdd(&cnt[bb[j]], 1);
                }
            }
            __syncthreads();
            if (tid == 0) {
                int s = 0, nt = 0;
                for (int i = 0; i < NB; i++) {
                    base[i] = s;
                    int c = cnt[i];
                    for (int off = 0; off < c; off += MTILE) {
                        int mc = c - off; if (mc > MTILE) mc = MTILE;
                        g_tinfo[hop][nt++] = i | ((s + off) << 6) | (mc << 17);
                    }
                    s += c;
                }
                g_ntiles[hop] = nt;
            }
            __syncthreads();
#pragma unroll
            for (int j = 0; j < 4; j++)
                if (act[j]) g_perm[hop][base[bb[j]] + rr[j]] = tid + 256 * j;
            __syncthreads();
        }
    }
}

// ============================================================
// 1) fused hop kernel: one CTA owns 8 tokens through BOTH layers.
//    h = relu(x@W1k + b1eff) lives in smem; state = relu(h@W2 + b2).
//    No global barrier between layers; 4 launches total for hops.
//    Thread map: og = tid&63 (64x4 outs = 256), tg = tid>>6
//    (tokens tg, tg+4).  W staged in triple-buffered 8x256 chunks,
//    prefetch distance 2 (~512 cyc cover > L2 latency).
// ============================================================
__global__ void __launch_bounds__(256, 1)
hop_kernel(int hop, const float* __restrict__ W1,
           const float* __restrict__ W2, const float* __restrict__ b2) {
    __shared__ float xs[MTILE * XS_STR];     //  8.3 KB
    __shared__ float hs[MTILE * XS_STR];     //  8.3 KB
    __shared__ float ws[3][KBF * HD];        // 24 KB
    __shared__ float cs[HD];                 //  1 KB
    __shared__ int   tok_s[MTILE];

    int nt  = g_ntiles[hop];
    int tid = threadIdx.x;
    int og  = tid & 63, tg = tid >> 6;

    for (int tix = blockIdx.x; tix < nt; tix += gridDim.x) {
        __syncthreads();                     // prev tile fully done
        int info = g_tinfo[hop][tix];
        int bkt  = info & 63;
        int poff = (info >> 6) & 2047;
        int mcnt = info >> 17;

        if (tid < MTILE) tok_s[tid] = (tid < mcnt) ? g_perm[hop][poff + tid] : -1;
        __syncthreads();

        // gather x tile: 8 tok x 64 float4, 2 per thread (zero-pad dead rows)
        {
            int r = tid >> 5, c4 = tid & 31;
            const float* src = (tok_s[r] >= 0) ? g_state + tok_s[r] * HD : 0;
            float4 v0 = src ? *(const float4*)(src + c4 * 4)
                            : make_float4(0.f, 0.f, 0.f, 0.f);
            float4 v1 = src ? *(const float4*)(src + (c4 + 32) * 4)
                            : make_float4(0.f, 0.f, 0.f, 0.f);
            *(float4*)(xs + r * XS_STR + c4 * 4)        = v0;
            *(float4*)(xs + r * XS_STR + (c4 + 32) * 4) = v1;
        }

#pragma unroll
        for (int layer = 0; layer < 2; layer++) {
            const float* Wb   = layer ? W2 + (size_t)bkt * W2STR
                                      : W1 + (size_t)bkt * W1STR;
            const float* bias = layer ? b2 + bkt * HD : g_b1eff + bkt * HD;
            const float* xin  = layer ? hs : xs;

            __syncthreads();     // xs/hs ready; prev epilogue done with cs
            cs[tid] = bias[tid];

            // stage chunks 0,1 (2 coalesced float4 per thread per chunk)
            int kl = tid >> 5, o4 = tid & 31;
            const float* wsrc = Wb + kl * HD + o4 * 4;
            {
                float4 a0 = *(const float4*)(wsrc);
                float4 a1 = *(const float4*)(wsrc + 128);
                float4 b0 = *(const float4*)(wsrc + KBF * HD);
                float4 b1v = *(const float4*)(wsrc + KBF * HD + 128);
                *(float4*)(&ws[0][kl * HD + o4 * 4])        = a0;
                *(float4*)(&ws[0][kl * HD + o4 * 4 + 128])  = a1;
                *(float4*)(&ws[1][kl * HD + o4 * 4])        = b0;
                *(float4*)(&ws[1][kl * HD + o4 * 4 + 128])  = b1v;
            }
            __syncthreads();

            float a00 = 0.f, a01 = 0.f, a02 = 0.f, a03 = 0.f;
            float a10 = 0.f, a11 = 0.f, a12 = 0.f, a13 = 0.f;
            const float* xr0 = xin + tg * XS_STR;
            const float* xr1 = xin + (tg + 4) * XS_STR;

            for (int c = 0; c < NCHF; c++) {
                float4 q0, q1;
                bool pf = (c + 2 < NCHF);
                if (pf) {
                    q0 = *(const float4*)(wsrc + (c + 2) * KBF * HD);
                    q1 = *(const float4*)(wsrc + (c + 2) * KBF * HD + 128);
                }
                const float* wb = &ws[c % 3][og * 4];
#pragma unroll
                for (int k4 = 0; k4 < KBF / 4; k4++) {
                    float4 xv0 = *(const float4*)(xr0 + c * KBF + k4 * 4);
                    float4 xv1 = *(const float4*)(xr1 + c * KBF + k4 * 4);
#pragma unroll
                    for (int j = 0; j < 4; j++) {
                        float4 w = *(const float4*)(wb + (k4 * 4 + j) * HD);
                        float x0 = (j == 0) ? xv0.x : (j == 1) ? xv0.y : (j == 2) ? xv0.z : xv0.w;
                        float x1 = (j == 0) ? xv1.x : (j == 1) ? xv1.y : (j == 2) ? xv1.z : xv1.w;
                        a00 += x0 * w.x; a01 += x0 * w.y; a02 += x0 * w.z; a03 += x0 * w.w;
                        a10 += x1 * w.x; a11 += x1 * w.y; a12 += x1 * w.z; a13 += x1 * w.w;
                    }
                }
                if (pf) {
                    float* dst = &ws[(c + 2) % 3][kl * HD + o4 * 4];
                    *(float4*)(dst)       = q0;
                    *(float4*)(dst + 128) = q1;
                }
                __syncthreads();
            }

            float c0 = cs[og * 4 + 0], c1 = cs[og * 4 + 1];
            float c2 = cs[og * 4 + 2], c3 = cs[og * 4 + 3];
            float4 r0, r1;
            r0.x = fmaxf(a00 + c0, 0.f); r0.y = fmaxf(a01 + c1, 0.f);
            r0.z = fmaxf(a02 + c2, 0.f); r0.w = fmaxf(a03 + c3, 0.f);
            r1.x = fmaxf(a10 + c0, 0.f); r1.y = fmaxf(a11 + c1, 0.f);
            r1.z = fmaxf(a12 + c2, 0.f); r1.w = fmaxf(a13 + c3, 0.f);

            if (layer == 0) {               // h -> smem (padded rows too; harmless)
                *(float4*)(hs + tg * XS_STR + og * 4)       = r0;
                *(float4*)(hs + (tg + 4) * XS_STR + og * 4) = r1;
            } else {                        // y -> state (active rows only)
                if (tg < mcnt)
                    *(float4*)(g_state + tok_s[tg] * HD + og * 4) = r0;
                if (tg + 4 < mcnt)
                    *(float4*)(g_state + tok_s[tg + 4] * HD + og * 4) = r1;
            }
        }
    }
}

// ============================================================
// 2) pool(8) + LayerNorm + 256x10 head.  Deterministic shuffle trees.
// ============================================================
__global__ void __launch_bounds__(256)
head_kernel(const float* __restrict__ ln_g, const float* __restrict__ ln_b,
            const float* __restrict__ Wt,   const float* __restrict__ bt,
            float* __restrict__ out) {
    int b = blockIdx.x, col = threadIdx.x;
    float s = 0.f;
#pragma unroll
    for (int p = 0; p < 8; p++) s += g_state[(b * 8 + p) * HD + col];
    float pooled = s * 0.125f;

    float v = pooled, v2 = pooled * pooled;
#pragma unroll
    for (int off = 16; off; off >>= 1) {
        v  += __shfl_down_sync(0xffffffffu, v,  off);
        v2 += __shfl_down_sync(0xffffffffu, v2, off);
    }
    __shared__ float wsum[8], wsum2[8];
    __shared__ float mu_s, rstd_s;
    int w = col >> 5, l = col & 31;
    if (l == 0) { wsum[w] = v; wsum2[w] = v2; }
    __syncthreads();
    if (col == 0) {
        float S = 0.f, S2 = 0.f;
#pragma unroll
        for (int i = 0; i < 8; i++) { S += wsum[i]; S2 += wsum2[i]; }
        float mu  = S * (1.f / 256.f);
        float var = S2 * (1.f / 256.f) - mu * mu;
        mu_s = mu; rstd_s = rsqrtf(var + 1e-5f);
    }
    __syncthreads();
    float normed = (pooled - mu_s) * rstd_s * ln_g[col] + ln_b[col];

    float p[10];
#pragma unroll
    for (int c = 0; c < 10; c++) p[c] = normed * Wt[col * 10 + c];
#pragma unroll
    for (int off = 16; off; off >>= 1)
#pragma unroll
        for (int c = 0; c < 10; c++) p[c] += __shfl_down_sync(0xffffffffu, p[c], off);

    __shared__ float pr[8][10];
    if (l == 0)
#pragma unroll
        for (int c = 0; c < 10; c++) pr[w][c] = p[c];
    __syncthreads();
    if (col < 10) {
        float acc = bt[col];
#pragma unroll
        for (int i = 0; i < 8; i++) acc += pr[i][col];
        out[b * 10 + col] = acc;
    }
}

// ============================================================
extern "C" void kernel_launch(void* const* d_in, const int* in_sizes, int n_in,
                              void* d_out, int out_size) {
    const float* x    = (const float*)d_in[0];
    const float* W1   = (const float*)d_in[1];
    const float* b1   = (const float*)d_in[2];
    const float* W2   = (const float*)d_in[3];
    const float* b2   = (const float*)d_in[4];
    const float* emb  = (const float*)d_in[5];
    const float* ln_g = (const float*)d_in[6];
    const float* ln_b = (const float*)d_in[7];
    const float* Wt   = (const float*)d_in[8];
    const float* bt   = (const float*)d_in[9];
    const int*   st   = (const int*)d_in[10];
    const int*   so   = (const int*)d_in[11];
    float* out = (float*)d_out;
    (void)in_sizes; (void)n_in; (void)out_size;

    prep_kernel<<<256 + NB + 1, 256>>>(x, W1, b1, emb, st, so);
    for (int hop = 0; hop < NHOPS; hop++)
        hop_kernel<<<MAXT, 256>>>(hop, W1, W2, b2);
    head_kernel<<<128, 256>>>(ln_g, ln_b, Wt, bt, out);
}